// round 11
// baseline (speedup 1.0000x reference)
#include <cuda_runtime.h>
#include <cstdint>
#include <cstddef>

// ============================================================================
// RhythmMemoryUpdater — GB300 sm_103a (base sm_103 target)
//   L = 1  =>  out = node_memories; out[node_ids] = LN( x @ W'^T + lin_b )
//   x = [messages | node_memories[node_ids]] (K=256)
//   W'[d,c] = lin_w[d,c] * conv_w[c, period/2]
//
// R11: bf16 MMA (m16n8k16) with STATIC W-SPLIT error compensation:
//   W' = Wh + Wl (both bf16, resident in regs). y = Wh*x + Wl*x with x bf16.
//   x fragments reused across both products -> crossbar stays halved vs tf32.
//   Residual error is x-rounding only (~8.4e-4 diluted, under 1e-3).
// ============================================================================

#define NDIM 128
#define KDIM 256
#define TILE_M 64
#define NTHREADS 512
#define NCTAS 148
#define SXB_STRIDE 132           // u32 (bf16-pair) units per staged row;
                                 // banks 4r+q all distinct -> conflict-free
#define SD_STRIDE 132            // floats per D row (conflict-free)

__device__ uint8_t g_mask[1 << 20];

// ---------------- helpers ----------------
__device__ __forceinline__ uint32_t pack_bf16(float lo, float hi) {
    uint32_t r;
    asm("cvt.rn.bf16x2.f32 %0, %1, %2;" : "=r"(r) : "f"(hi), "f"(lo));
    return r;
}
__device__ __forceinline__ void mma_bf16(float c[4], uint32_t a0, uint32_t a1,
                                         uint32_t a2, uint32_t a3,
                                         uint32_t b0, uint32_t b1) {
    asm volatile(
        "mma.sync.aligned.m16n8k16.row.col.f32.bf16.bf16.f32 "
        "{%0,%1,%2,%3}, {%4,%5,%6,%7}, {%8,%9}, {%0,%1,%2,%3};"
        : "+f"(c[0]), "+f"(c[1]), "+f"(c[2]), "+f"(c[3])
        : "r"(a0), "r"(a1), "r"(a2), "r"(a3), "r"(b0), "r"(b1));
}

// ============================================================================
// mask + copy kernels
// ============================================================================
__global__ void __launch_bounds__(256) k_clear(int nbytes16) {
    uint4 z = make_uint4(0, 0, 0, 0);
    uint4* m = (uint4*)g_mask;
    for (int i = blockIdx.x * 256 + threadIdx.x; i < nbytes16; i += gridDim.x * 256)
        m[i] = z;
}
__global__ void __launch_bounds__(256) k_mark(const int* __restrict__ ids, int n) {
    int i = blockIdx.x * 256 + threadIdx.x;
    if (i < n) g_mask[ids[i]] = 1;
}
__global__ void __launch_bounds__(256) k_copy_masked(const float4* __restrict__ src,
                                                     float4* __restrict__ dst,
                                                     int nf4) {
    int stride = gridDim.x * 256;
    for (int i = blockIdx.x * 256 + threadIdx.x; i < nf4; i += stride) {
        int row = i >> 5;
        if (g_mask[row] == 0) dst[i] = src[i];
    }
}

// ============================================================================
// persistent GEMM + LayerNorm + scatter
// ============================================================================
__global__ void __launch_bounds__(NTHREADS, 1) rhythm_gemm(
    const int*   __restrict__ node_ids,
    const float* __restrict__ messages,
    const float* __restrict__ node_mem,
    const float* __restrict__ conv_w,
    const float* __restrict__ lin_w,
    const float* __restrict__ lin_b,
    const float* __restrict__ ln_g,
    const float* __restrict__ ln_bt,
    float*       __restrict__ out,
    int ntiles, int period, int pad)
{
    // ---- dynamic smem carve ----
    extern __shared__ uint32_t dyn[];
    uint32_t* sXb    = dyn;                                    // 2*64*132 u32
    float4*   s_comb = (float4*)(dyn + 2 * TILE_M * SXB_STRIDE);   // 2048 f4
    float*    sD     = (float*)(s_comb + 2048);                // 64*132 f
    int*      s_node = (int*)(sD + TILE_M * SD_STRIDE);        // 2*64
    float*    s_gam  = (float*)(s_node + 2 * TILE_M);          // 128
    float*    s_bet  = s_gam + NDIM;                           // 128

    const int tid  = threadIdx.x;
    const int lane = tid & 31;
    const int wid  = tid >> 5;        // 0..15
    const int kh   = wid >> 3;        // K-half: 0 -> k 0..127, 1 -> 128..255
    const int dblk = wid & 7;         // d block

    // ---- static per-warp W' fragments, SPLIT: Wh + Wl (bf16x2 each) ----
    const int d1 = dblk * 16 + (lane >> 2);
    const int d2 = d1 + 8;

    uint32_t aregH[8][4], aregL[8][4];
#pragma unroll
    for (int kt = 0; kt < 8; kt++) {
        int k1 = kh * 128 + kt * 16 + (lane & 3) * 2;
#pragma unroll
        for (int h = 0; h < 2; h++) {          // h=0 -> k1, h=1 -> k1+8
            int kk = k1 + 8 * h;
            float wa = __ldg(conv_w + kk * period + pad);
            float wb = __ldg(conv_w + (kk + 1) * period + pad);
            float w10 = __ldg(lin_w + d1 * KDIM + kk) * wa;
            float w11 = __ldg(lin_w + d1 * KDIM + kk + 1) * wb;
            float w20 = __ldg(lin_w + d2 * KDIM + kk) * wa;
            float w21 = __ldg(lin_w + d2 * KDIM + kk + 1) * wb;
            uint32_t h1 = pack_bf16(w10, w11);
            uint32_t h2 = pack_bf16(w20, w21);
            aregH[kt][2 * h]     = h1;
            aregH[kt][2 * h + 1] = h2;
            // residuals: exact bf16 back-conversion is bits<<16 / bits&hi16
            float r10 = w10 - __uint_as_float(h1 << 16);
            float r11 = w11 - __uint_as_float(h1 & 0xffff0000u);
            float r20 = w20 - __uint_as_float(h2 << 16);
            float r21 = w21 - __uint_as_float(h2 & 0xffff0000u);
            aregL[kt][2 * h]     = pack_bf16(r10, r11);
            aregL[kt][2 * h + 1] = pack_bf16(r20, r21);
        }
    }
    const float bia1 = __ldg(lin_b + d1), bia2 = __ldg(lin_b + d2);
    if (tid < NDIM) {
        s_gam[tid] = ln_g[tid];
        s_bet[tid] = ln_bt[tid];
    }

    const float4* msg4 = (const float4*)messages;
    const float4* mem4 = (const float4*)node_mem;

    // ---- staging: loads + pack + stores, done in one shot (slot is free) ----
    auto stage_tile = [&](int tile, int it_idx) {
        const int slot = it_idx & 1;
        uint32_t* dstS = sXb + (size_t)slot * TILE_M * SXB_STRIDE;
        float4 v[8];
#pragma unroll
        for (int i = 0; i < 8; i++) {
            int idx = i * NTHREADS + tid;
            int row = idx >> 6, c = idx & 63;
            long long gr = (long long)tile * TILE_M + row;
            if (c < 32) {
                v[i] = msg4[gr * 32 + c];
            } else {
                int nd = __ldg(node_ids + gr);
                if (c == 32) s_node[slot * TILE_M + row] = nd;
                v[i] = mem4[(long long)nd * 32 + (c - 32)];
            }
        }
#pragma unroll
        for (int i = 0; i < 8; i++) {
            int idx = i * NTHREADS + tid;
            int row = idx >> 6, c = idx & 63;
            *(uint2*)&dstS[row * SXB_STRIDE + 2 * c] =
                make_uint2(pack_bf16(v[i].x, v[i].y), pack_bf16(v[i].z, v[i].w));
        }
    };

    // ---- prologue: stage tile 0 ----
    if (blockIdx.x < ntiles) stage_tile(blockIdx.x, 0);

    for (int it = 0;; it++) {
        int tile = blockIdx.x + it * gridDim.x;
        if (tile >= ntiles) break;
        const int slot = it & 1;

        __syncthreads();          // staged slot + s_node (+ s_gam first iter)

        // ======== MMA: per warp 16 d x 64 batch, K-half, Wh + Wl ========
        const uint32_t* xb = sXb + (size_t)slot * TILE_M * SXB_STRIDE
                           + (lane >> 2) * SXB_STRIDE + kh * 64 + (lane & 3);
        float cacc[8][4];
#pragma unroll
        for (int nt = 0; nt < 8; nt++)
#pragma unroll
            for (int j = 0; j < 4; j++) cacc[nt][j] = 0.f;

#pragma unroll
        for (int kt = 0; kt < 8; kt++) {
            uint32_t b[16];
#pragma unroll
            for (int nt = 0; nt < 8; nt++) {
                const uint32_t* xp = xb + nt * 8 * SXB_STRIDE + kt * 8;
                b[2 * nt]     = xp[0];
                b[2 * nt + 1] = xp[4];
            }
#pragma unroll
            for (int nt = 0; nt < 8; nt++) {
                mma_bf16(cacc[nt], aregH[kt][0], aregH[kt][1],
                         aregH[kt][2], aregH[kt][3], b[2 * nt], b[2 * nt + 1]);
                mma_bf16(cacc[nt], aregL[kt][0], aregL[kt][1],
                         aregL[kt][2], aregL[kt][3], b[2 * nt], b[2 * nt + 1]);
            }
        }

        // ---- K-high warps publish partials ----
        if (kh == 1) {
#pragma unroll
            for (int nt = 0; nt < 8; nt++)
                s_comb[(dblk * 8 + nt) * 32 + lane] =
                    make_float4(cacc[nt][0], cacc[nt][1], cacc[nt][2], cacc[nt][3]);
        }
        __syncthreads();          // sX slot reads done + s_comb visible

        // ---- stage tile it+1 into slot^1 (free: last read was it-1 MMA) ----
        int ntile = tile + gridDim.x;
        if (ntile < ntiles) stage_tile(ntile, it + 1);

        // ---- K-low warps: combine + bias -> sD (conflict-free STS) ----
        if (kh == 0) {
#pragma unroll
            for (int nt = 0; nt < 8; nt++) {
                float4 p = s_comb[(dblk * 8 + nt) * 32 + lane];
                int brA = nt * 8 + (lane & 3) * 2;
                sD[brA * SD_STRIDE + d1]       = cacc[nt][0] + p.x + bia1;
                sD[(brA + 1) * SD_STRIDE + d1] = cacc[nt][1] + p.y + bia1;
                sD[brA * SD_STRIDE + d2]       = cacc[nt][2] + p.z + bia2;
                sD[(brA + 1) * SD_STRIDE + d2] = cacc[nt][3] + p.w + bia2;
            }
        }
        __syncthreads();          // sD complete

        // ---- LayerNorm + coalesced scatter: ALL 512 threads ----
        {
            const int r  = tid >> 3;       // row 0..63
            const int cc = tid & 7;        // f4-chunks cc, cc+8, cc+16, cc+24
            float4 v[4];
            float vsum = 0.f, vsq = 0.f;
#pragma unroll
            for (int j = 0; j < 4; j++) {
                v[j] = *(const float4*)&sD[r * SD_STRIDE + (cc + 8 * j) * 4];
                vsum += v[j].x + v[j].y + v[j].z + v[j].w;
                vsq  += v[j].x * v[j].x + v[j].y * v[j].y
                      + v[j].z * v[j].z + v[j].w * v[j].w;
            }
            vsum += __shfl_xor_sync(0xffffffffu, vsum, 1);
            vsq  += __shfl_xor_sync(0xffffffffu, vsq, 1);
            vsum += __shfl_xor_sync(0xffffffffu, vsum, 2);
            vsq  += __shfl_xor_sync(0xffffffffu, vsq, 2);
            vsum += __shfl_xor_sync(0xffffffffu, vsum, 4);
            vsq  += __shfl_xor_sync(0xffffffffu, vsq, 4);
            float mean = vsum * (1.0f / 128.0f);
            float var  = vsq * (1.0f / 128.0f) - mean * mean;
            float rstd = rsqrtf(var + 1e-5f);

            long long nd = s_node[slot * TILE_M + r];
            float* orow = out + nd * NDIM;
#pragma unroll
            for (int j = 0; j < 4; j++) {
                int cb = (cc + 8 * j) * 4;
                const float4 g  = *(const float4*)&s_gam[cb];
                const float4 bt = *(const float4*)&s_bet[cb];
                float4 o;
                o.x = (v[j].x - mean) * rstd * g.x + bt.x;
                o.y = (v[j].y - mean) * rstd * g.y + bt.y;
                o.z = (v[j].z - mean) * rstd * g.z + bt.z;
                o.w = (v[j].w - mean) * rstd * g.w + bt.w;
                *(float4*)&orow[cb] = o;
            }
        }
        // loop-top __syncthreads publishes staged slot before next MMA
    }
}

// ============================================================================
// launch
// ============================================================================
extern "C" void kernel_launch(void* const* d_in, const int* in_sizes, int n_in,
                              void* d_out, int out_size) {
    const int*   node_ids = (const int*)  d_in[0];
    const float* messages = (const float*)d_in[1];
    const float* node_mem = (const float*)d_in[2];
    const float* conv_w   = (const float*)d_in[3];
    const float* lin_w    = (const float*)d_in[4];
    const float* lin_b    = (const float*)d_in[5];
    const float* ln_g     = (const float*)d_in[6];
    const float* ln_bt    = (const float*)d_in[7];
    float* out = (float*)d_out;

    int Btot    = in_sizes[1] / NDIM;            // 262144
    int ntiles  = Btot / TILE_M;                 // 4096
    int period  = in_sizes[3] / KDIM;            // 7
    int pad     = period / 2;                    // 3 (L == 1 path)
    int nf4     = out_size / 4;

    // mask of rows updated by the scatter
    k_clear<<<64, 256>>>((1 << 20) / 16);
    k_mark<<<(Btot + 255) / 256, 256>>>(node_ids, Btot);

    // copy non-updated rows at full occupancy
    k_copy_masked<<<2048, 256>>>((const float4*)node_mem, (float4*)out, nf4);

    // persistent GEMM + LN + scatter
    const int dyn_smem = 2 * TILE_M * SXB_STRIDE * 4      // x bf16 ping-pong
                       + 2048 * 16                        // s_comb
                       + TILE_M * SD_STRIDE * 4           // sD
                       + 2 * TILE_M * 4 + 2 * NDIM * 4;   // node ring + ln vecs
    static int configured = -1;
    if (configured != dyn_smem) {
        cudaFuncSetAttribute(rhythm_gemm, cudaFuncAttributeMaxDynamicSharedMemorySize,
                             dyn_smem);
        configured = dyn_smem;
    }
    rhythm_gemm<<<NCTAS, NTHREADS, dyn_smem>>>(node_ids, messages, node_mem, conv_w,
                                               lin_w, lin_b, ln_g, ln_bt, out,
                                               ntiles, period, pad);
}